// round 3
// baseline (speedup 1.0000x reference)
#include <cuda_runtime.h>
#include <cstdint>

// Problem constants
#define BB   32
#define TT   6
#define CC   128
#define HH   32
#define WW   32
#define NIMG (BB * TT)          // 192 images per conv
#define HW   (HH * WW)          // 1024
#define CHW  (CC * HW)          // 131072
#define CI_CHUNK 8

// Scratch: y / spike buffer, reused in place by the scan. 100.7 MB static.
__device__ float g_ybuf[(size_t)NIMG * CHW];

// Packed f32x2 helpers (Blackwell sm_100+: one issue slot = two fp32 FMAs)
__device__ __forceinline__ unsigned long long bcast_f32x2(float v) {
    unsigned long long r;
    asm("mov.b64 %0, {%1, %1};" : "=l"(r) : "f"(v));
    return r;
}
__device__ __forceinline__ void fma_f32x2(unsigned long long& d,
                                          unsigned long long a,
                                          unsigned long long b) {
    asm("fma.rn.f32x2 %0, %1, %2, %0;" : "+l"(d) : "l"(a), "l"(b));
}
__device__ __forceinline__ void unpack_f32x2(unsigned long long v,
                                             float& lo, float& hi) {
    asm("mov.b64 {%0, %1}, %2;" : "=f"(lo), "=f"(hi) : "l"(v));
}

// ---------------------------------------------------------------------------
// 3x3 SAME conv, 128->128 channels, fp32 direct conv, packed f32x2 FMAs.
// Block = (pair of output rows, image). 256 threads:
//   pxg = t & 7        -> 8 groups of 4 output columns (32 cols)
//   ocg = (t >> 3)&15  -> 16 groups of 8 output channels (128 oc)
//   row = t >> 7       -> 2 output rows per block
// Thread tile: 8 oc x 4 px. K-loop over input channels in chunks of 8.
// ---------------------------------------------------------------------------
template <bool CLIP>
__global__ __launch_bounds__(256)
void conv3x3_kernel(const float* __restrict__ x,
                    const float* __restrict__ w,      // [oc][ci][3][3]
                    const float* __restrict__ bias,   // [oc]
                    const float* __restrict__ alpha,  // scalar (device)
                    float* __restrict__ out)
{
    // weights chunk, transposed: index = (ci*9 + kh*3 + kw) * 128 + oc
    __shared__ float s_w[CI_CHUNK * 9 * 128];          // 36 KB
    // input slab: (ci*4 + r) * 36 + j ; img col = j-1 (halo), rows h0-1..h0+2
    __shared__ float s_in[CI_CHUNK * 4 * 36];          // 4.6 KB

    const int h0  = blockIdx.x * 2;      // first output row of the pair
    const int n   = blockIdx.y;          // image
    const int t   = threadIdx.x;
    const int px0 = (t & 7) * 4;
    const int oc0 = ((t >> 3) & 15) * 8;
    const int row = t >> 7;              // 0 or 1

    // acc[q][p]: packed pair (oc0+2q, oc0+2q+1) at pixel px0+p
    unsigned long long acc[4][4];
#pragma unroll
    for (int q = 0; q < 4; q++)
#pragma unroll
        for (int p = 0; p < 4; p++) acc[q][p] = 0ull;

    const float* xn = x + (size_t)n * CHW;

    for (int ci0 = 0; ci0 < CC; ci0 += CI_CHUNK) {
        // --- load weight chunk (dst-contiguous stores: no STS conflicts) ---
        for (int idx = t; idx < CI_CHUNK * 9 * 128; idx += 256) {
            int oc  = idx & 127;
            int cik = idx >> 7;              // ci*9 + k, 0..71
            int ci  = cik / 9;
            int k   = cik - ci * 9;
            s_w[idx] = w[((size_t)oc * CC + ci0 + ci) * 9 + k];
        }
        // --- load input slab (4 rows + halo cols, zero-padded) ---
        for (int idx = t; idx < CI_CHUNK * 4 * 36; idx += 256) {
            int j  = idx % 36;
            int rc = idx / 36;
            int r  = rc & 3;
            int ci = rc >> 2;
            int col = j - 1;
            int grow = h0 + r - 1;
            float v = 0.0f;
            if (col >= 0 && col < WW && grow >= 0 && grow < HH)
                v = xn[(size_t)(ci0 + ci) * HW + grow * WW + col];
            s_in[idx] = v;
        }
        __syncthreads();

        // --- compute -----------------------------------------------------
#pragma unroll
        for (int ci = 0; ci < CI_CHUNK; ci++) {
#pragma unroll
            for (int kh = 0; kh < 3; kh++) {
                // input row for this thread's output row: slab r = row + kh
                const float* sr = &s_in[(ci * 4 + row + kh) * 36 + px0];
                unsigned long long xx[6];
#pragma unroll
                for (int j = 0; j < 6; j++) xx[j] = bcast_f32x2(sr[j]);
#pragma unroll
                for (int kw = 0; kw < 3; kw++) {
                    const float* wp = &s_w[(ci * 9 + kh * 3 + kw) * 128 + oc0];
                    const ulonglong2 w01 = *(const ulonglong2*)(wp);     // oc0..3
                    const ulonglong2 w23 = *(const ulonglong2*)(wp + 4); // oc4..7
#pragma unroll
                    for (int p = 0; p < 4; p++) {
                        fma_f32x2(acc[0][p], w01.x, xx[p + kw]);
                        fma_f32x2(acc[1][p], w01.y, xx[p + kw]);
                        fma_f32x2(acc[2][p], w23.x, xx[p + kw]);
                        fma_f32x2(acc[3][p], w23.y, xx[p + kw]);
                    }
                }
            }
        }
        __syncthreads();
    }

    // --- epilogue: bias (+ optional PACT clip), vectorized stores ---
    const float a = CLIP ? *alpha : 0.0f;
    const int   h = h0 + row;
#pragma unroll
    for (int q = 0; q < 4; q++) {
        float lo[4], hi[4];
#pragma unroll
        for (int p = 0; p < 4; p++) unpack_f32x2(acc[q][p], lo[p], hi[p]);

        const float b0 = bias[oc0 + 2 * q];
        const float b1 = bias[oc0 + 2 * q + 1];
        float4 r0, r1;
        float* p0 = (float*)&r0;
        float* p1 = (float*)&r1;
#pragma unroll
        for (int p = 0; p < 4; p++) {
            float v0 = lo[p] + b0;
            float v1 = hi[p] + b1;
            if (CLIP) {
                v0 = fminf(fmaxf(v0, 0.0f), a);
                v1 = fminf(fmaxf(v1, 0.0f), a);
            }
            p0[p] = v0;
            p1[p] = v1;
        }
        *(float4*)&out[((size_t)n * CC + oc0 + 2 * q)     * HW + h * WW + px0] = r0;
        *(float4*)&out[((size_t)n * CC + oc0 + 2 * q + 1) * HW + h * WW + px0] = r1;
    }
}

// ---------------------------------------------------------------------------
// Temporal LIF scan over T=6, in place on the y buffer.
// One thread per (b, c, h, w); strides over t by CHW.
// ---------------------------------------------------------------------------
__global__ __launch_bounds__(256)
void scan_kernel(float* __restrict__ y, const float* __restrict__ alpha)
{
    int idx = blockIdx.x * blockDim.x + threadIdx.x;
    if (idx >= BB * CHW) return;
    int b   = idx / CHW;
    int rem = idx - b * CHW;
    float* p = y + (size_t)b * TT * CHW + rem;

    const float thr = *alpha;
    float mem = 0.5f * thr;
    float ss  = 0.0f;
#pragma unroll
    for (int tt = 0; tt < TT; tt++) {
        float xt = p[(size_t)tt * CHW];
        mem += xt;
        float spike = (mem >= thr) ? 1.0f : 0.0f;
        mem -= thr * spike;
        ss  += spike;
        float inhib = (mem <= -0.001f && ss > 0.0f) ? 1.0f : 0.0f;
        mem += thr * inhib;
        ss  -= inhib;
        p[(size_t)tt * CHW] = (spike - inhib) * thr;
    }
}

// ---------------------------------------------------------------------------
extern "C" void kernel_launch(void* const* d_in, const int* in_sizes, int n_in,
                              void* d_out, int out_size)
{
    const float* x      = (const float*)d_in[0];
    const float* w_pre  = (const float*)d_in[1];
    const float* b_pre  = (const float*)d_in[2];
    const float* alpha  = (const float*)d_in[3];
    const float* w_post = (const float*)d_in[4];
    const float* b_post = (const float*)d_in[5];
    float*       out    = (float*)d_out;

    float* ybuf = nullptr;
    cudaGetSymbolAddress((void**)&ybuf, g_ybuf);   // no alloc; address query only

    dim3 grid(HH / 2, NIMG);   // (16 row-pairs, 192 images)
    conv3x3_kernel<true ><<<grid, 256>>>(x, w_pre, b_pre, alpha, ybuf);
    scan_kernel<<<(BB * CHW + 255) / 256, 256>>>(ybuf, alpha);
    conv3x3_kernel<false><<<grid, 256>>>(ybuf, w_post, b_post, alpha, out);
}

// round 10
// speedup vs baseline: 1.3110x; 1.3110x over previous
#include <cuda_runtime.h>
#include <cstdint>

// Problem constants
#define BB   32
#define TT   6
#define CC   128
#define HH   32
#define WW   32
#define NIMG (BB * TT)          // 192 images per conv
#define HW   (HH * WW)          // 1024
#define CHW  (CC * HW)          // 131072
#define CI_CHUNK 8

// Scratch: y / spike buffer, reused in place by the scan. 100.7 MB static.
__device__ float g_ybuf[(size_t)NIMG * CHW];

// Packed f32x2 helpers (Blackwell sm_100+: one issue slot = two fp32 FMAs)
__device__ __forceinline__ unsigned long long bcast_f32x2(float v) {
    unsigned long long r;
    asm("mov.b64 %0, {%1, %1};" : "=l"(r) : "f"(v));
    return r;
}
__device__ __forceinline__ void fma_f32x2(unsigned long long& d,
                                          unsigned long long a,
                                          unsigned long long b) {
    asm("fma.rn.f32x2 %0, %1, %2, %0;" : "+l"(d) : "l"(a), "l"(b));
}
__device__ __forceinline__ void unpack_f32x2(unsigned long long v,
                                             float& lo, float& hi) {
    asm("mov.b64 {%0, %1}, %2;" : "=f"(lo), "=f"(hi) : "l"(v));
}

// ---------------------------------------------------------------------------
// 3x3 SAME conv, 128->128 channels, fp32 direct conv, packed f32x2 FMAs.
// Block = (4 output rows, image). 256 threads:
//   pxg = t & 3        -> 4 groups of 8 output columns (32 cols)
//   ocg = (t >> 2)&15  -> 16 groups of 8 output channels (128 oc)
//   row = t >> 6       -> 4 output rows per block
// Thread tile: 8 oc x 8 px (32 packed f32x2 accumulators).
// smem bytes per FMA2 cut 2.5x vs the 4-px tile (R3 was L1TEX-bound at 92%).
// ---------------------------------------------------------------------------
template <bool CLIP>
__global__ __launch_bounds__(256, 1)
void conv3x3_kernel(const float* __restrict__ x,
                    const float* __restrict__ w,      // [oc][ci][3][3]
                    const float* __restrict__ bias,   // [oc]
                    const float* __restrict__ alpha,  // scalar (device)
                    float* __restrict__ out)
{
    // weights chunk, transposed: index = (ci*9 + kh*3 + kw) * 128 + oc
    __shared__ __align__(16) float s_w[CI_CHUNK * 9 * 128];   // 36 KB
    // input slab: (ci*6 + r) * 36 + j ; img col = j-1 (halo), rows h0-1..h0+4
    __shared__ __align__(16) float s_in[CI_CHUNK * 6 * 36];   // 6.75 KB

    const int h0  = blockIdx.x * 4;      // first output row of the quad
    const int n   = blockIdx.y;          // image
    const int t   = threadIdx.x;
    const int px0 = (t & 3) * 8;
    const int oc0 = ((t >> 2) & 15) * 8;
    const int row = t >> 6;              // 0..3

    // acc[q][p]: packed pair (oc0+2q, oc0+2q+1) at pixel px0+p
    unsigned long long acc[4][8];
#pragma unroll
    for (int q = 0; q < 4; q++)
#pragma unroll
        for (int p = 0; p < 8; p++) acc[q][p] = 0ull;

    const float* xn = x + (size_t)n * CHW;

    for (int ci0 = 0; ci0 < CC; ci0 += CI_CHUNK) {
        // --- load weight chunk (dst-contiguous stores: no STS conflicts) ---
        for (int idx = t; idx < CI_CHUNK * 9 * 128; idx += 256) {
            int oc  = idx & 127;
            int cik = idx >> 7;              // ci*9 + k, 0..71
            int ci  = cik / 9;
            int k   = cik - ci * 9;
            s_w[idx] = w[((size_t)oc * CC + ci0 + ci) * 9 + k];
        }
        // --- load input slab (6 rows + halo cols, zero-padded) ---
        for (int idx = t; idx < CI_CHUNK * 6 * 36; idx += 256) {
            int j  = idx % 36;
            int rc = idx / 36;
            int r  = rc % 6;
            int ci = rc / 6;
            int col  = j - 1;
            int grow = h0 + r - 1;
            float v = 0.0f;
            if (col >= 0 && col < WW && grow >= 0 && grow < HH)
                v = xn[(size_t)(ci0 + ci) * HW + grow * WW + col];
            s_in[idx] = v;
        }
        __syncthreads();

        // --- compute -----------------------------------------------------
#pragma unroll
        for (int ci = 0; ci < CI_CHUNK; ci++) {
#pragma unroll
            for (int kh = 0; kh < 3; kh++) {
                // input row for this thread's output row: slab r = row + kh
                const float* sr = &s_in[(ci * 6 + row + kh) * 36 + px0];
                // need sr[0..9]; rows are 144B (16B multiple), px0*4 is 32B
                const float4 va = *(const float4*)(sr);
                const float4 vb = *(const float4*)(sr + 4);
                const float4 vc = *(const float4*)(sr + 8);
                unsigned long long xx[10];
                xx[0] = bcast_f32x2(va.x); xx[1] = bcast_f32x2(va.y);
                xx[2] = bcast_f32x2(va.z); xx[3] = bcast_f32x2(va.w);
                xx[4] = bcast_f32x2(vb.x); xx[5] = bcast_f32x2(vb.y);
                xx[6] = bcast_f32x2(vb.z); xx[7] = bcast_f32x2(vb.w);
                xx[8] = bcast_f32x2(vc.x); xx[9] = bcast_f32x2(vc.y);
#pragma unroll
                for (int kw = 0; kw < 3; kw++) {
                    const float* wp = &s_w[(ci * 9 + kh * 3 + kw) * 128 + oc0];
                    const ulonglong2 w01 = *(const ulonglong2*)(wp);     // oc0..3
                    const ulonglong2 w23 = *(const ulonglong2*)(wp + 4); // oc4..7
#pragma unroll
                    for (int p = 0; p < 8; p++) {
                        fma_f32x2(acc[0][p], w01.x, xx[p + kw]);
                        fma_f32x2(acc[1][p], w01.y, xx[p + kw]);
                        fma_f32x2(acc[2][p], w23.x, xx[p + kw]);
                        fma_f32x2(acc[3][p], w23.y, xx[p + kw]);
                    }
                }
            }
        }
        __syncthreads();
    }

    // --- epilogue: bias (+ optional PACT clip), vectorized stores ---
    const float a = CLIP ? *alpha : 0.0f;
    const int   h = h0 + row;
#pragma unroll
    for (int q = 0; q < 4; q++) {
        float lo[8], hi[8];
#pragma unroll
        for (int p = 0; p < 8; p++) unpack_f32x2(acc[q][p], lo[p], hi[p]);

        const float b0 = bias[oc0 + 2 * q];
        const float b1 = bias[oc0 + 2 * q + 1];
        float r0[8], r1[8];
#pragma unroll
        for (int p = 0; p < 8; p++) {
            float v0 = lo[p] + b0;
            float v1 = hi[p] + b1;
            if (CLIP) {
                v0 = fminf(fmaxf(v0, 0.0f), a);
                v1 = fminf(fmaxf(v1, 0.0f), a);
            }
            r0[p] = v0;
            r1[p] = v1;
        }
        float* o0 = &out[((size_t)n * CC + oc0 + 2 * q)     * HW + h * WW + px0];
        float* o1 = &out[((size_t)n * CC + oc0 + 2 * q + 1) * HW + h * WW + px0];
        *(float4*)(o0)     = *(float4*)&r0[0];
        *(float4*)(o0 + 4) = *(float4*)&r0[4];
        *(float4*)(o1)     = *(float4*)&r1[0];
        *(float4*)(o1 + 4) = *(float4*)&r1[4];
    }
}

// ---------------------------------------------------------------------------
// Temporal LIF scan over T=6, in place on the y buffer, float4-vectorized.
// One thread per 4 consecutive (c,h,w) elements; strides over t by CHW.
// ---------------------------------------------------------------------------
__global__ __launch_bounds__(256)
void scan_kernel(float* __restrict__ y, const float* __restrict__ alpha)
{
    int idx = blockIdx.x * blockDim.x + threadIdx.x;     // float4 index
    const int NV = (BB * CHW) / 4;
    if (idx >= NV) return;
    int b   = idx / (CHW / 4);
    int rem = idx - b * (CHW / 4);
    float4* p = (float4*)(y + (size_t)b * TT * CHW) + rem;

    const float thr = *alpha;
    float mem[4], ss[4];
#pragma unroll
    for (int e = 0; e < 4; e++) { mem[e] = 0.5f * thr; ss[e] = 0.0f; }
#pragma unroll
    for (int tt = 0; tt < TT; tt++) {
        float4 xv = p[(size_t)tt * (CHW / 4)];
        float* xe = (float*)&xv;
#pragma unroll
        for (int e = 0; e < 4; e++) {
            mem[e] += xe[e];
            float spike = (mem[e] >= thr) ? 1.0f : 0.0f;
            mem[e] -= thr * spike;
            ss[e]  += spike;
            float inhib = (mem[e] <= -0.001f && ss[e] > 0.0f) ? 1.0f : 0.0f;
            mem[e] += thr * inhib;
            ss[e]  -= inhib;
            xe[e] = (spike - inhib) * thr;
        }
        p[(size_t)tt * (CHW / 4)] = xv;
    }
}

// ---------------------------------------------------------------------------
extern "C" void kernel_launch(void* const* d_in, const int* in_sizes, int n_in,
                              void* d_out, int out_size)
{
    const float* x      = (const float*)d_in[0];
    const float* w_pre  = (const float*)d_in[1];
    const float* b_pre  = (const float*)d_in[2];
    const float* alpha  = (const float*)d_in[3];
    const float* w_post = (const float*)d_in[4];
    const float* b_post = (const float*)d_in[5];
    float*       out    = (float*)d_out;

    float* ybuf = nullptr;
    cudaGetSymbolAddress((void**)&ybuf, g_ybuf);   // no alloc; address query only

    dim3 grid(HH / 4, NIMG);   // (8 row-quads, 192 images)
    conv3x3_kernel<true ><<<grid, 256>>>(x, w_pre, b_pre, alpha, ybuf);
    scan_kernel<<<(BB * CHW / 4 + 255) / 256, 256>>>(ybuf, alpha);
    conv3x3_kernel<false><<<grid, 256>>>(ybuf, w_post, b_post, alpha, out);
}

// round 14
// speedup vs baseline: 2.0301x; 1.5485x over previous
#include <cuda_runtime.h>
#include <cstdint>

// Problem constants
#define BB   32
#define TT   6
#define CC   128
#define HH   32
#define WW   32
#define NIMG (BB * TT)          // 192 images per conv
#define HW   (HH * WW)          // 1024
#define CHW  (CC * HW)          // 131072
#define CI_CHUNK 8
#define WELEM (CC * CC * 9)     // 147456 weights per conv

// Scratch: y / spike buffer, reused in place by the scan. 100.7 MB static.
__device__ float g_ybuf[(size_t)NIMG * CHW];
// Pre-transposed weights: [(ci*9 + k) * 128 + oc]
__device__ float g_wt0[WELEM];
__device__ float g_wt1[WELEM];

// Packed f32x2 helpers (Blackwell sm_100+: one issue slot = two fp32 FMAs)
__device__ __forceinline__ unsigned long long bcast_f32x2(float v) {
    unsigned long long r;
    asm("mov.b64 %0, {%1, %1};" : "=l"(r) : "f"(v));
    return r;
}
__device__ __forceinline__ void fma_f32x2(unsigned long long& d,
                                          unsigned long long a,
                                          unsigned long long b) {
    asm("fma.rn.f32x2 %0, %1, %2, %0;" : "+l"(d) : "l"(a), "l"(b));
}
__device__ __forceinline__ void unpack_f32x2(unsigned long long v,
                                             float& lo, float& hi) {
    asm("mov.b64 {%0, %1}, %2;" : "=f"(lo), "=f"(hi) : "l"(v));
}
// cp.async 16B gmem->smem (Ampere+ LDGSTS; no register round-trip)
__device__ __forceinline__ void cp_async16(void* smem, const void* gmem) {
    uint32_t s = (uint32_t)__cvta_generic_to_shared(smem);
    asm volatile("cp.async.cg.shared.global [%0], [%1], 16;\n" :: "r"(s), "l"(gmem));
}
__device__ __forceinline__ void cp_async_commit_wait0() {
    asm volatile("cp.async.commit_group;\n");
    asm volatile("cp.async.wait_group 0;\n" ::: "memory");
}

// ---------------------------------------------------------------------------
// Weight transpose: w[oc][ci][k] -> wt[(ci*9+k)*128 + oc]
// ---------------------------------------------------------------------------
__global__ __launch_bounds__(256)
void transpose_w_kernel(const float* __restrict__ w, float* __restrict__ wt)
{
    int idx = blockIdx.x * 256 + threadIdx.x;
    if (idx >= WELEM) return;
    int oc  = idx / (CC * 9);
    int rem = idx - oc * (CC * 9);      // ci*9 + k
    wt[rem * CC + oc] = w[idx];
}

// ---------------------------------------------------------------------------
// 3x3 SAME conv, 128->128 channels, fp32 direct conv, packed f32x2 FMAs.
// Block = (4 output rows, image). 256 threads:
//   pxg = t & 3, ocg = (t>>2)&15, row = t>>6. Thread tile: 8 oc x 8 px.
// Weights pre-transposed; chunk fill = 9 contiguous cp.async 16B per thread.
// ---------------------------------------------------------------------------
template <bool CLIP>
__global__ __launch_bounds__(256, 1)
void conv3x3_kernel(const float* __restrict__ x,
                    const float* __restrict__ wt,     // transposed weights
                    const float* __restrict__ bias,   // [oc]
                    const float* __restrict__ alpha,  // scalar (device)
                    float* __restrict__ out)
{
    // weights chunk: index = (ci*9 + kh*3 + kw) * 128 + oc
    __shared__ __align__(16) float s_w[CI_CHUNK * 9 * 128];   // 36 KB
    // input slab: (ci*6 + r) * 36 + j ; img col = j-1 (halo), rows h0-1..h0+4
    __shared__ __align__(16) float s_in[CI_CHUNK * 6 * 36];   // 6.75 KB

    const int h0  = blockIdx.x * 4;      // first output row of the quad
    const int n   = blockIdx.y;          // image
    const int t   = threadIdx.x;
    const int px0 = (t & 3) * 8;
    const int oc0 = ((t >> 2) & 15) * 8;
    const int row = t >> 6;              // 0..3

    // acc[q][p]: packed pair (oc0+2q, oc0+2q+1) at pixel px0+p
    unsigned long long acc[4][8];
#pragma unroll
    for (int q = 0; q < 4; q++)
#pragma unroll
        for (int p = 0; p < 8; p++) acc[q][p] = 0ull;

    const float* xn = x + (size_t)n * CHW;

    for (int ci0 = 0; ci0 < CC; ci0 += CI_CHUNK) {
        // --- weight chunk via cp.async: 2304 float4, 9 per thread, coalesced
        {
            const float4* wsrc = (const float4*)(wt + (size_t)ci0 * 9 * CC);
            float4*       wdst = (float4*)s_w;
#pragma unroll
            for (int k = 0; k < 9; k++)
                cp_async16(wdst + k * 256 + t, wsrc + k * 256 + t);
        }
        // --- input slab (6 rows + halo cols, zero-padded); overlaps cp.async
        for (int idx = t; idx < CI_CHUNK * 6 * 36; idx += 256) {
            int j  = idx % 36;
            int rc = idx / 36;
            int r  = rc % 6;
            int ci = rc / 6;
            int col  = j - 1;
            int grow = h0 + r - 1;
            float v = 0.0f;
            if (col >= 0 && col < WW && grow >= 0 && grow < HH)
                v = xn[(size_t)(ci0 + ci) * HW + grow * WW + col];
            s_in[idx] = v;
        }
        cp_async_commit_wait0();
        __syncthreads();

        // --- compute -----------------------------------------------------
#pragma unroll
        for (int ci = 0; ci < CI_CHUNK; ci++) {
#pragma unroll
            for (int kh = 0; kh < 3; kh++) {
                // input row for this thread's output row: slab r = row + kh
                const float* sr = &s_in[(ci * 6 + row + kh) * 36 + px0];
                // need sr[0..9]; rows are 144B (16B multiple), px0*4 is 32B
                const float4 va = *(const float4*)(sr);
                const float4 vb = *(const float4*)(sr + 4);
                const float4 vc = *(const float4*)(sr + 8);
                unsigned long long xx[10];
                xx[0] = bcast_f32x2(va.x); xx[1] = bcast_f32x2(va.y);
                xx[2] = bcast_f32x2(va.z); xx[3] = bcast_f32x2(va.w);
                xx[4] = bcast_f32x2(vb.x); xx[5] = bcast_f32x2(vb.y);
                xx[6] = bcast_f32x2(vb.z); xx[7] = bcast_f32x2(vb.w);
                xx[8] = bcast_f32x2(vc.x); xx[9] = bcast_f32x2(vc.y);
#pragma unroll
                for (int kw = 0; kw < 3; kw++) {
                    const float* wp = &s_w[(ci * 9 + kh * 3 + kw) * 128 + oc0];
                    const ulonglong2 w01 = *(const ulonglong2*)(wp);     // oc0..3
                    const ulonglong2 w23 = *(const ulonglong2*)(wp + 4); // oc4..7
#pragma unroll
                    for (int p = 0; p < 8; p++) {
                        fma_f32x2(acc[0][p], w01.x, xx[p + kw]);
                        fma_f32x2(acc[1][p], w01.y, xx[p + kw]);
                        fma_f32x2(acc[2][p], w23.x, xx[p + kw]);
                        fma_f32x2(acc[3][p], w23.y, xx[p + kw]);
                    }
                }
            }
        }
        __syncthreads();
    }

    // --- epilogue: bias (+ optional PACT clip), vectorized stores ---
    const float a = CLIP ? *alpha : 0.0f;
    const int   h = h0 + row;
#pragma unroll
    for (int q = 0; q < 4; q++) {
        float lo[8], hi[8];
#pragma unroll
        for (int p = 0; p < 8; p++) unpack_f32x2(acc[q][p], lo[p], hi[p]);

        const float b0 = bias[oc0 + 2 * q];
        const float b1 = bias[oc0 + 2 * q + 1];
        float r0[8], r1[8];
#pragma unroll
        for (int p = 0; p < 8; p++) {
            float v0 = lo[p] + b0;
            float v1 = hi[p] + b1;
            if (CLIP) {
                v0 = fminf(fmaxf(v0, 0.0f), a);
                v1 = fminf(fmaxf(v1, 0.0f), a);
            }
            r0[p] = v0;
            r1[p] = v1;
        }
        float* o0 = &out[((size_t)n * CC + oc0 + 2 * q)     * HW + h * WW + px0];
        float* o1 = &out[((size_t)n * CC + oc0 + 2 * q + 1) * HW + h * WW + px0];
        *(float4*)(o0)     = *(float4*)&r0[0];
        *(float4*)(o0 + 4) = *(float4*)&r0[4];
        *(float4*)(o1)     = *(float4*)&r1[0];
        *(float4*)(o1 + 4) = *(float4*)&r1[4];
    }
}

// ---------------------------------------------------------------------------
// Temporal LIF scan over T=6, in place on the y buffer, float4-vectorized.
// ---------------------------------------------------------------------------
__global__ __launch_bounds__(256)
void scan_kernel(float* __restrict__ y, const float* __restrict__ alpha)
{
    int idx = blockIdx.x * blockDim.x + threadIdx.x;     // float4 index
    const int NV = (BB * CHW) / 4;
    if (idx >= NV) return;
    int b   = idx / (CHW / 4);
    int rem = idx - b * (CHW / 4);
    float4* p = (float4*)(y + (size_t)b * TT * CHW) + rem;

    const float thr = *alpha;
    float mem[4], ss[4];
#pragma unroll
    for (int e = 0; e < 4; e++) { mem[e] = 0.5f * thr; ss[e] = 0.0f; }
#pragma unroll
    for (int tt = 0; tt < TT; tt++) {
        float4 xv = p[(size_t)tt * (CHW / 4)];
        float* xe = (float*)&xv;
#pragma unroll
        for (int e = 0; e < 4; e++) {
            mem[e] += xe[e];
            float spike = (mem[e] >= thr) ? 1.0f : 0.0f;
            mem[e] -= thr * spike;
            ss[e]  += spike;
            float inhib = (mem[e] <= -0.001f && ss[e] > 0.0f) ? 1.0f : 0.0f;
            mem[e] += thr * inhib;
            ss[e]  -= inhib;
            xe[e] = (spike - inhib) * thr;
        }
        p[(size_t)tt * (CHW / 4)] = xv;
    }
}

// ---------------------------------------------------------------------------
extern "C" void kernel_launch(void* const* d_in, const int* in_sizes, int n_in,
                              void* d_out, int out_size)
{
    const float* x      = (const float*)d_in[0];
    const float* w_pre  = (const float*)d_in[1];
    const float* b_pre  = (const float*)d_in[2];
    const float* alpha  = (const float*)d_in[3];
    const float* w_post = (const float*)d_in[4];
    const float* b_post = (const float*)d_in[5];
    float*       out    = (float*)d_out;

    float *ybuf = nullptr, *wt0 = nullptr, *wt1 = nullptr;
    cudaGetSymbolAddress((void**)&ybuf, g_ybuf);   // no alloc; address queries
    cudaGetSymbolAddress((void**)&wt0, g_wt0);
    cudaGetSymbolAddress((void**)&wt1, g_wt1);

    const int tgrid = (WELEM + 255) / 256;
    transpose_w_kernel<<<tgrid, 256>>>(w_pre, wt0);
    transpose_w_kernel<<<tgrid, 256>>>(w_post, wt1);

    dim3 grid(HH / 4, NIMG);   // (8 row-quads, 192 images)
    conv3x3_kernel<true ><<<grid, 256>>>(x, wt0, b_pre, alpha, ybuf);
    scan_kernel<<<(BB * CHW / 4 + 255) / 256, 256>>>(ybuf, alpha);
    conv3x3_kernel<false><<<grid, 256>>>(ybuf, wt1, b_post, alpha, out);
}